// round 1
// baseline (speedup 1.0000x reference)
#include <cuda_runtime.h>
#include <cstdint>
#include <math.h>

#define NTOK   16384
#define DIN    2048
#define DOUT   2048
#define RANKL  16
#define NEXP   16
#define LORA   256      // NEXP * RANKL
#define KCAT   2304     // DIN + LORA

// ---------------- scratch (static device arrays; no runtime allocation) ------------
__device__ float g_xt[NTOK * DIN];        // tf32-rounded x            (134 MB)
__device__ float g_wmat[DOUT * KCAT];     // [o][k] : W | Bcat, tf32   (18.9 MB)
__device__ float g_acat[LORA * DIN];      // [j][k] : A reshaped, tf32 (2 MB)
__device__ float g_wxa[NTOK * LORA];      // coeff-weighted xa, tf32   (16.8 MB)
__device__ float g_coeff[NTOK * NEXP];    // dense router coeffs       (1 MB)

// ---------------- helpers ----------------------------------------------------------
__device__ __forceinline__ float tf32r(float x) {
    uint32_t u;
    asm("cvt.rna.tf32.f32 %0, %1;" : "=r"(u) : "f"(x));
    return __uint_as_float(u);
}

__device__ __forceinline__ void cp16(float* s, const float* g) {
    uint32_t sa = (uint32_t)__cvta_generic_to_shared(s);
    asm volatile("cp.async.cg.shared.global [%0], [%1], 16;\n" :: "r"(sa), "l"(g) : "memory");
}
__device__ __forceinline__ void cp_commit() {
    asm volatile("cp.async.commit_group;\n" ::: "memory");
}

__device__ __forceinline__ void mma8(float c[4], const uint32_t a[4], const uint32_t b[2]) {
    asm volatile(
        "mma.sync.aligned.m16n8k8.row.col.f32.tf32.tf32.f32 "
        "{%0,%1,%2,%3},{%4,%5,%6,%7},{%8,%9},{%0,%1,%2,%3};\n"
        : "+f"(c[0]), "+f"(c[1]), "+f"(c[2]), "+f"(c[3])
        : "r"(a[0]), "r"(a[1]), "r"(a[2]), "r"(a[3]), "r"(b[0]), "r"(b[1]));
}

// ---------------- prep: build tf32-rounded weight matrices --------------------------
// g_wmat[o][k] = W[o][k] for k<2048, = B[e][o][r] for k = 2048 + e*16 + r
// g_acat[j][k] = A flattened (already [256][2048] contiguous)
__global__ void prep_kernel(const float* __restrict__ W, const float* __restrict__ B,
                            const float* __restrict__ A) {
    int idx = blockIdx.x * 256 + threadIdx.x;
    const int NW = DOUT * KCAT;
    if (idx < NW) {
        int o = idx / KCAT, k = idx - o * KCAT;
        float v;
        if (k < DIN) {
            v = W[o * DIN + k];
        } else {
            int j = k - DIN;
            int e = j >> 4, r = j & 15;
            v = B[(e * DOUT + o) * RANKL + r];
        }
        g_wmat[idx] = tf32r(v);
    } else {
        int i = idx - NW;
        if (i < LORA * DIN) g_acat[i] = tf32r(A[i]);
    }
}

// ---------------- tf32-round x ------------------------------------------------------
__global__ void cvtx_kernel(const float4* __restrict__ x) {
    int i = blockIdx.x * 256 + threadIdx.x;
    float4 v = x[i];
    v.x = tf32r(v.x); v.y = tf32r(v.y); v.z = tf32r(v.z); v.w = tf32r(v.w);
    reinterpret_cast<float4*>(g_xt)[i] = v;
}

// ---------------- router (fp32 exact path) ------------------------------------------
// One warp per token. h = silu(x@rw1^T + rb1); logits = (h@rw2^T + rb2)[:16] + gates;
// top-2 (ties -> lower index, matching jax top_k), softmax, scatter into g_coeff.
__global__ __launch_bounds__(128)
void router_kernel(const float* __restrict__ x, const float* __restrict__ rw1,
                   const float* __restrict__ rb1, const float* __restrict__ rw2,
                   const float* __restrict__ rb2, const float* __restrict__ gates) {
    __shared__ float xs[4][DIN];
    __shared__ float hs[4][64];
    const int lane = threadIdx.x & 31;
    const int warp = threadIdx.x >> 5;
    const int tok  = blockIdx.x * 4 + warp;

    const float4* xr  = reinterpret_cast<const float4*>(x + (size_t)tok * DIN);
    float4*       xsv = reinterpret_cast<float4*>(xs[warp]);
    #pragma unroll 4
    for (int i = lane; i < DIN / 4; i += 32) xsv[i] = xr[i];
    __syncwarp();

    float a0 = 0.f, a1 = 0.f;
    const float4* w0 = reinterpret_cast<const float4*>(rw1 + (size_t)lane * DIN);
    const float4* w1 = reinterpret_cast<const float4*>(rw1 + (size_t)(lane + 32) * DIN);
    for (int i = 0; i < DIN / 4; i++) {
        float4 xv = xsv[i];
        float4 u = w0[i], v = w1[i];
        a0 += xv.x * u.x + xv.y * u.y + xv.z * u.z + xv.w * u.w;
        a1 += xv.x * v.x + xv.y * v.y + xv.z * v.z + xv.w * v.w;
    }
    a0 += rb1[lane]; a1 += rb1[lane + 32];
    a0 = a0 / (1.f + expf(-a0));   // silu
    a1 = a1 / (1.f + expf(-a1));
    hs[warp][lane] = a0; hs[warp][lane + 32] = a1;
    __syncwarp();

    const float NEGINF = __int_as_float(0xff800000);
    float logit = NEGINF;
    if (lane < NEXP) {
        float s = rb2[lane] + gates[lane];
        const float* w2 = rw2 + lane * 64;
        #pragma unroll
        for (int h = 0; h < 64; h++) s += hs[warp][h] * w2[h];
        logit = s;
    }

    // top-1 (strict >, ties keep lower index)
    float v = logit; int idx = (lane < NEXP) ? lane : 1000;
    #pragma unroll
    for (int off = 8; off; off >>= 1) {
        float ov = __shfl_down_sync(0xffffffffu, v, off);
        int   oi = __shfl_down_sync(0xffffffffu, idx, off);
        if (ov > v || (ov == v && oi < idx)) { v = ov; idx = oi; }
    }
    float v1 = __shfl_sync(0xffffffffu, v, 0);
    int   i1 = __shfl_sync(0xffffffffu, idx, 0);

    // top-2
    v = (lane == i1) ? NEGINF : logit;
    idx = (lane < NEXP && lane != i1) ? lane : 1000;
    #pragma unroll
    for (int off = 8; off; off >>= 1) {
        float ov = __shfl_down_sync(0xffffffffu, v, off);
        int   oi = __shfl_down_sync(0xffffffffu, idx, off);
        if (ov > v || (ov == v && oi < idx)) { v = ov; idx = oi; }
    }
    float v2 = __shfl_sync(0xffffffffu, v, 0);
    int   i2 = __shfl_sync(0xffffffffu, idx, 0);

    float e   = expf(v2 - v1);
    float inv = 1.f / (1.f + e);
    float p1  = inv, p2 = e * inv;
    if (lane < NEXP) {
        float c = (lane == i1) ? p1 : ((lane == i2) ? p2 : 0.f);
        g_coeff[tok * NEXP + lane] = c;
    }
}

// ---------------- tf32 tiled GEMM ---------------------------------------------------
// C[M,N] = Arow[M,K] * B[N,K]^T   (A row-major, B row-major as [n][k] = mma "col")
// MODE 0: epilogue wxa = tf32(coeff[row][col>>4] * acc)   (C = g_wxa)
// MODE 1: A has two K-regions (x for k<ksplit, wxa beyond); epilogue adds bias.
template<int MODE>
__device__ __forceinline__ void load_tile(
    float* as, float* bs, int kt,
    const float* A1, int lda1, int ksplit, const float* A2, int lda2,
    const float* Bm, int ldb, int mBase, int nBase, int arow, int ac4) {
    int k0 = kt << 5;
    #pragma unroll
    for (int j = 0; j < 4; j++) {
        int row  = arow + j * 32;
        int soff = row * 32 + (ac4 ^ ((row & 7) << 2));
        const float* srcA = (MODE == 1 && k0 >= ksplit)
            ? A2 + (size_t)(mBase + row) * lda2 + (k0 - ksplit) + ac4
            : A1 + (size_t)(mBase + row) * lda1 + k0 + ac4;
        cp16(as + soff, srcA);
        cp16(bs + soff, Bm + (size_t)(nBase + row) * ldb + k0 + ac4);
    }
    cp_commit();
}

template<int MODE>
__global__ __launch_bounds__(256)
void gemm_tf32(const float* __restrict__ A1, int lda1, int ksplit,
               const float* __restrict__ A2, int lda2,
               const float* __restrict__ Bm, int ldb,
               const float* __restrict__ aux,   // bias (MODE1) / coeff (MODE0)
               float* __restrict__ C, int ldc, int K) {
    extern __shared__ float smf[];
    float* As = smf;                 // 2 x 128 x 32
    float* Bs = smf + 2 * 128 * 32;

    const int t    = threadIdx.x;
    const int lane = t & 31, warp = t >> 5;
    const int wm = warp >> 2, wn = warp & 3;     // 2 x 4 warp grid
    const int qrow = lane >> 2, qcol = lane & 3;
    const int sw = qrow << 2;                    // xor swizzle per lane

    const int arow = t >> 3;
    const int ac4  = (t & 7) << 2;
    const int mBase = blockIdx.y * 128;
    const int nBase = blockIdx.x * 128;

    float acc[4][4][4];
    #pragma unroll
    for (int a = 0; a < 4; a++)
        #pragma unroll
        for (int b = 0; b < 4; b++)
            #pragma unroll
            for (int r = 0; r < 4; r++) acc[a][b][r] = 0.f;

    const int nTiles = K >> 5;
    load_tile<MODE>(As, Bs, 0, A1, lda1, ksplit, A2, lda2, Bm, ldb, mBase, nBase, arow, ac4);

    for (int kt = 0; kt < nTiles; kt++) {
        int buf = kt & 1;
        if (kt + 1 < nTiles) {
            load_tile<MODE>(As + (buf ^ 1) * 4096, Bs + (buf ^ 1) * 4096, kt + 1,
                            A1, lda1, ksplit, A2, lda2, Bm, ldb, mBase, nBase, arow, ac4);
            asm volatile("cp.async.wait_group 1;\n" ::: "memory");
        } else {
            asm volatile("cp.async.wait_group 0;\n" ::: "memory");
        }
        __syncthreads();

        const uint32_t* as = reinterpret_cast<const uint32_t*>(As + buf * 4096);
        const uint32_t* bs = reinterpret_cast<const uint32_t*>(Bs + buf * 4096);
        #pragma unroll
        for (int kk = 0; kk < 4; kk++) {
            uint32_t af[4][4], bf[4][2];
            #pragma unroll
            for (int fm = 0; fm < 4; fm++) {
                int r0 = wm * 64 + fm * 16 + qrow;
                int c0 = kk * 8 + qcol;
                af[fm][0] = as[r0 * 32 + (c0 ^ sw)];
                af[fm][1] = as[(r0 + 8) * 32 + (c0 ^ sw)];
                af[fm][2] = as[r0 * 32 + ((c0 + 4) ^ sw)];
                af[fm][3] = as[(r0 + 8) * 32 + ((c0 + 4) ^ sw)];
            }
            #pragma unroll
            for (int fn = 0; fn < 4; fn++) {
                int ro = wn * 32 + fn * 8 + qrow;
                int c0 = kk * 8 + qcol;
                bf[fn][0] = bs[ro * 32 + (c0 ^ sw)];
                bf[fn][1] = bs[ro * 32 + ((c0 + 4) ^ sw)];
            }
            #pragma unroll
            for (int fm = 0; fm < 4; fm++)
                #pragma unroll
                for (int fn = 0; fn < 4; fn++)
                    mma8(acc[fm][fn], af[fm], bf[fn]);
        }
        __syncthreads();
    }

    // epilogue
    #pragma unroll
    for (int fm = 0; fm < 4; fm++) {
        int r0 = mBase + wm * 64 + fm * 16 + qrow;
        #pragma unroll
        for (int fn = 0; fn < 4; fn++) {
            int c0 = nBase + wn * 32 + fn * 8 + qcol * 2;
            if (MODE == 1) {
                float b0 = aux[c0], b1 = aux[c0 + 1];
                float2 v0 = make_float2(acc[fm][fn][0] + b0, acc[fm][fn][1] + b1);
                float2 v1 = make_float2(acc[fm][fn][2] + b0, acc[fm][fn][3] + b1);
                *reinterpret_cast<float2*>(C + (size_t)r0 * ldc + c0) = v0;
                *reinterpret_cast<float2*>(C + (size_t)(r0 + 8) * ldc + c0) = v1;
            } else {
                float s0 = aux[r0 * NEXP + (c0 >> 4)];
                float s1 = aux[(r0 + 8) * NEXP + (c0 >> 4)];
                float2 v0 = make_float2(tf32r(s0 * acc[fm][fn][0]), tf32r(s0 * acc[fm][fn][1]));
                float2 v1 = make_float2(tf32r(s1 * acc[fm][fn][2]), tf32r(s1 * acc[fm][fn][3]));
                *reinterpret_cast<float2*>(C + (size_t)r0 * ldc + c0) = v0;
                *reinterpret_cast<float2*>(C + (size_t)(r0 + 8) * ldc + c0) = v1;
            }
        }
    }
}

// ---------------- launch ------------------------------------------------------------
extern "C" void kernel_launch(void* const* d_in, const int* in_sizes, int n_in,
                              void* d_out, int out_size) {
    const float* x     = (const float*)d_in[0];
    const float* W     = (const float*)d_in[1];
    const float* bias  = (const float*)d_in[2];
    const float* rw1   = (const float*)d_in[3];
    const float* rb1   = (const float*)d_in[4];
    const float* rw2   = (const float*)d_in[5];
    const float* rb2   = (const float*)d_in[6];
    const float* A     = (const float*)d_in[7];
    const float* B     = (const float*)d_in[8];
    const float* gates = (const float*)d_in[9];
    float* out = (float*)d_out;

    cudaFuncSetAttribute(gemm_tf32<0>, cudaFuncAttributeMaxDynamicSharedMemorySize, 65536);
    cudaFuncSetAttribute(gemm_tf32<1>, cudaFuncAttributeMaxDynamicSharedMemorySize, 65536);

    void *p_xt, *p_wmat, *p_acat, *p_wxa, *p_coeff;
    cudaGetSymbolAddress(&p_xt, g_xt);
    cudaGetSymbolAddress(&p_wmat, g_wmat);
    cudaGetSymbolAddress(&p_acat, g_acat);
    cudaGetSymbolAddress(&p_wxa, g_wxa);
    cudaGetSymbolAddress(&p_coeff, g_coeff);

    // 1) tf32-round weights (W | Bcat) and Acat
    prep_kernel<<<20480, 256>>>(W, B, A);
    // 2) tf32-round x
    cvtx_kernel<<<32768, 256>>>(reinterpret_cast<const float4*>(x));
    // 3) router (fp32 exact) -> g_coeff
    router_kernel<<<4096, 128>>>(x, rw1, rb1, rw2, rb2, gates);
    // 4) xa = x @ Acat^T, epilogue wxa = tf32(coeff * xa)     [M=16384, N=256, K=2048]
    gemm_tf32<0><<<dim3(2, 128), 256, 65536>>>(
        (const float*)p_xt, DIN, DIN, nullptr, 0,
        (const float*)p_acat, DIN,
        (const float*)p_coeff, (float*)p_wxa, LORA, DIN);
    // 5) out = [x | wxa] @ [W^T ; Bcat] + bias               [M=16384, N=2048, K=2304]
    gemm_tf32<1><<<dim3(16, 128), 256, 65536>>>(
        (const float*)p_xt, DIN, DIN,
        (const float*)p_wxa, LORA,
        (const float*)p_wmat, KCAT,
        bias, out, DOUT, KCAT);
}

// round 4
// speedup vs baseline: 2.5694x; 2.5694x over previous
#include <cuda_runtime.h>
#include <cstdint>
#include <math.h>

#define NTOK   16384
#define DIN    2048
#define DOUT   2048
#define RANKL  16
#define NEXP   16
#define LORA   256      // NEXP * RANKL
#define KCAT   2304     // DIN + LORA
#define RHID   64

// ---------------- scratch (static device arrays; no runtime allocation) ------------
__device__ float g_xt[NTOK * DIN];        // tf32-rounded x
__device__ float g_wmat[DOUT * KCAT];     // [o][k] : W | Bcat, tf32
__device__ float g_acat[LORA * DIN];      // [j][k] : A reshaped, tf32
__device__ float g_wxa[NTOK * LORA];      // coeff-weighted xa, tf32
__device__ float g_coeff[NTOK * NEXP];    // dense router coeffs
__device__ float g_rw1t[DIN * RHID];      // rw1 transposed [k][n], fp32
__device__ float g_h[NTOK * RHID];        // router hidden, fp32

// ---------------- helpers ----------------------------------------------------------
__device__ __forceinline__ float tf32r(float x) {
    uint32_t u;
    asm("cvt.rna.tf32.f32 %0, %1;" : "=r"(u) : "f"(x));
    return __uint_as_float(u);
}
__device__ __forceinline__ void cp16(float* s, const float* g) {
    uint32_t sa = (uint32_t)__cvta_generic_to_shared(s);
    asm volatile("cp.async.cg.shared.global [%0], [%1], 16;\n" :: "r"(sa), "l"(g) : "memory");
}
__device__ __forceinline__ void cp_commit() {
    asm volatile("cp.async.commit_group;\n" ::: "memory");
}
__device__ __forceinline__ void mma8(float c[4], const uint32_t a[4], const uint32_t b[2]) {
    asm volatile(
        "mma.sync.aligned.m16n8k8.row.col.f32.tf32.tf32.f32 "
        "{%0,%1,%2,%3},{%4,%5,%6,%7},{%8,%9},{%0,%1,%2,%3};\n"
        : "+f"(c[0]), "+f"(c[1]), "+f"(c[2]), "+f"(c[3])
        : "r"(a[0]), "r"(a[1]), "r"(a[2]), "r"(a[3]), "r"(b[0]), "r"(b[1]));
}

// ---------------- prep: tf32-rounded weights + transposed rw1 -----------------------
__global__ void prep_kernel(const float* __restrict__ W, const float* __restrict__ B,
                            const float* __restrict__ A, const float* __restrict__ rw1) {
    int idx = blockIdx.x * 256 + threadIdx.x;
    const int NW = DOUT * KCAT;
    const int NA = LORA * DIN;
    if (idx < NW) {
        int o = idx / KCAT, k = idx - o * KCAT;
        float v;
        if (k < DIN) v = W[o * DIN + k];
        else {
            int j = k - DIN;
            v = B[((j >> 4) * DOUT + o) * RANKL + (j & 15)];
        }
        g_wmat[idx] = tf32r(v);
    } else if (idx < NW + NA) {
        int i = idx - NW;
        g_acat[i] = tf32r(A[i]);
    } else {
        int i = idx - NW - NA;
        if (i < DIN * RHID) {
            int k = i >> 6, n = i & 63;
            g_rw1t[i] = rw1[n * DIN + k];
        }
    }
}

// ---------------- tf32-round x ------------------------------------------------------
__global__ void cvtx_kernel(const float4* __restrict__ x) {
    int i = blockIdx.x * 256 + threadIdx.x;
    float4 v = x[i];
    v.x = tf32r(v.x); v.y = tf32r(v.y); v.z = tf32r(v.z); v.w = tf32r(v.w);
    reinterpret_cast<float4*>(g_xt)[i] = v;
}

// ---------------- router stage 1: h = silu(x @ rw1^T + rb1), fp32 SIMT GEMM ---------
#define WS_STRIDE 68
__global__ __launch_bounds__(256)
void hgemm_router(const float* __restrict__ x, const float* __restrict__ rb1) {
    extern __shared__ float sh[];
    float* xs = sh;              // 2 stages of 128*32
    float* ws = sh + 8192;       // 2 stages of 32*WS_STRIDE

    const int t = threadIdx.x;
    const int mBase = blockIdx.x * 128;

    const int arow = t >> 3;          // 0..31
    const int ac4  = (t & 7) << 2;    // 0..28
    const int wr   = t >> 3;          // 0..31 (k row)
    const int wc   = (t & 7) << 3;    // 0,8,...,56

    const int tx = t & 15;            // n group
    const int ty = t >> 4;            // m group
    const int n0 = tx * 4;
    const int m0 = ty * 8;

    float acc[8][4];
    #pragma unroll
    for (int i = 0; i < 8; i++)
        #pragma unroll
        for (int j = 0; j < 4; j++) acc[i][j] = 0.f;

    const int nTiles = DIN / 32;

    auto load = [&](int buf, int kt) {
        int k0 = kt << 5;
        float* xb = xs + buf * 4096;
        float* wb = ws + buf * 32 * WS_STRIDE;
        #pragma unroll
        for (int j = 0; j < 4; j++) {
            int row = arow + j * 32;
            cp16(xb + row * 32 + ac4, x + (size_t)(mBase + row) * DIN + k0 + ac4);
        }
        cp16(wb + wr * WS_STRIDE + wc,     g_rw1t + (size_t)(k0 + wr) * RHID + wc);
        cp16(wb + wr * WS_STRIDE + wc + 4, g_rw1t + (size_t)(k0 + wr) * RHID + wc + 4);
        cp_commit();
    };

    load(0, 0);
    for (int kt = 0; kt < nTiles; kt++) {
        int buf = kt & 1;
        if (kt + 1 < nTiles) {
            load(buf ^ 1, kt + 1);
            asm volatile("cp.async.wait_group 1;\n" ::: "memory");
        } else {
            asm volatile("cp.async.wait_group 0;\n" ::: "memory");
        }
        __syncthreads();

        const float* xb = xs + buf * 4096;
        const float* wb = ws + buf * 32 * WS_STRIDE;
        #pragma unroll
        for (int k4 = 0; k4 < 8; k4++) {
            float4 b[4];
            #pragma unroll
            for (int kk = 0; kk < 4; kk++)
                b[kk] = *reinterpret_cast<const float4*>(wb + (k4 * 4 + kk) * WS_STRIDE + n0);
            #pragma unroll
            for (int i = 0; i < 8; i++) {
                float4 av = *reinterpret_cast<const float4*>(xb + (m0 + i) * 32 + k4 * 4);
                #pragma unroll
                for (int j = 0; j < 4; j++) {
                    float bj = (j == 0 ? b[0].x : j == 1 ? b[0].y : j == 2 ? b[0].z : b[0].w);
                    float b1 = (j == 0 ? b[1].x : j == 1 ? b[1].y : j == 2 ? b[1].z : b[1].w);
                    float b2 = (j == 0 ? b[2].x : j == 1 ? b[2].y : j == 2 ? b[2].z : b[2].w);
                    float b3 = (j == 0 ? b[3].x : j == 1 ? b[3].y : j == 2 ? b[3].z : b[3].w);
                    acc[i][j] += av.x * bj + av.y * b1 + av.z * b2 + av.w * b3;
                }
            }
        }
        __syncthreads();
    }

    #pragma unroll
    for (int i = 0; i < 8; i++) {
        int tok = mBase + m0 + i;
        float4 o;
        float v0 = acc[i][0] + rb1[n0 + 0];
        float v1 = acc[i][1] + rb1[n0 + 1];
        float v2 = acc[i][2] + rb1[n0 + 2];
        float v3 = acc[i][3] + rb1[n0 + 3];
        o.x = v0 / (1.f + expf(-v0));
        o.y = v1 / (1.f + expf(-v1));
        o.z = v2 / (1.f + expf(-v2));
        o.w = v3 / (1.f + expf(-v3));
        *reinterpret_cast<float4*>(g_h + (size_t)tok * RHID + n0) = o;
    }
}

// ---------------- router stage 2: logits, top-2, softmax, coeff ---------------------
__global__ __launch_bounds__(256)
void top2_kernel(const float* __restrict__ rw2, const float* __restrict__ rb2,
                 const float* __restrict__ gates) {
    const int lane = threadIdx.x & 31;
    const int warp = threadIdx.x >> 5;
    const int tok  = blockIdx.x * 8 + warp;
    const float NEGINF = __int_as_float(0xff800000);

    const float* h = g_h + (size_t)tok * RHID;
    float logit = NEGINF;
    if (lane < NEXP) {
        float s = rb2[lane] + gates[lane];
        const float* w2 = rw2 + lane * RHID;
        #pragma unroll
        for (int k = 0; k < RHID; k++) s += h[k] * w2[k];
        logit = s;
    }

    float v = logit; int idx = (lane < NEXP) ? lane : 1000;
    #pragma unroll
    for (int off = 8; off; off >>= 1) {
        float ov = __shfl_down_sync(0xffffffffu, v, off);
        int   oi = __shfl_down_sync(0xffffffffu, idx, off);
        if (ov > v || (ov == v && oi < idx)) { v = ov; idx = oi; }
    }
    float v1 = __shfl_sync(0xffffffffu, v, 0);
    int   i1 = __shfl_sync(0xffffffffu, idx, 0);

    v = (lane == i1) ? NEGINF : logit;
    idx = (lane < NEXP && lane != i1) ? lane : 1000;
    #pragma unroll
    for (int off = 8; off; off >>= 1) {
        float ov = __shfl_down_sync(0xffffffffu, v, off);
        int   oi = __shfl_down_sync(0xffffffffu, idx, off);
        if (ov > v || (ov == v && oi < idx)) { v = ov; idx = oi; }
    }
    float v2 = __shfl_sync(0xffffffffu, v, 0);
    int   i2 = __shfl_sync(0xffffffffu, idx, 0);

    float e   = expf(v2 - v1);
    float inv = 1.f / (1.f + e);
    if (lane < NEXP) {
        float c = (lane == i1) ? inv : ((lane == i2) ? e * inv : 0.f);
        g_coeff[tok * NEXP + lane] = c;
    }
}

// ---------------- tf32 tiled GEMM: CTA 128x256, warp 64x64, 3-stage -----------------
// C[M,N] = Arow[M,K] * B[N,K]^T
// MODE 0: epilogue wxa = tf32(coeff[row][col>>4] * acc)
// MODE 1: A split at ksplit (x then wxa); epilogue adds bias.
#define STG_FLOATS 12288   // (128+256)*32

template<int MODE>
__global__ __launch_bounds__(256, 1)
void gemm_tf32(const float* __restrict__ A1, int lda1, int ksplit,
               const float* __restrict__ A2, int lda2,
               const float* __restrict__ Bm, int ldb,
               const float* __restrict__ aux,
               float* __restrict__ C, int ldc, int K) {
    extern __shared__ float smf[];

    const int t    = threadIdx.x;
    const int lane = t & 31, warp = t >> 5;
    const int wm = warp >> 2, wn = warp & 3;     // 2 x 4 warp grid (M x N)
    const int qrow = lane >> 2, qcol = lane & 3;
    const int sw = qrow << 2;

    const int arow = t >> 3;
    const int ac4  = (t & 7) << 2;
    const int mBase = blockIdx.y * 128;
    const int nBase = blockIdx.x * 256;

    float acc[4][8][4];
    #pragma unroll
    for (int a = 0; a < 4; a++)
        #pragma unroll
        for (int b = 0; b < 8; b++)
            #pragma unroll
            for (int r = 0; r < 4; r++) acc[a][b][r] = 0.f;

    const int nTiles = K >> 5;

    auto load_tile = [&](int stage, int kt) {
        float* as = smf + stage * STG_FLOATS;
        float* bs = as + 4096;
        int k0 = kt << 5;
        #pragma unroll
        for (int j = 0; j < 4; j++) {
            int row  = arow + j * 32;
            int soff = row * 32 + (ac4 ^ ((row & 7) << 2));
            const float* srcA = (MODE == 1 && k0 >= ksplit)
                ? A2 + (size_t)(mBase + row) * lda2 + (k0 - ksplit) + ac4
                : A1 + (size_t)(mBase + row) * lda1 + k0 + ac4;
            cp16(as + soff, srcA);
        }
        #pragma unroll
        for (int j = 0; j < 8; j++) {
            int row  = arow + j * 32;
            int soff = row * 32 + (ac4 ^ ((row & 7) << 2));
            cp16(bs + soff, Bm + (size_t)(nBase + row) * ldb + k0 + ac4);
        }
        cp_commit();
    };

    load_tile(0, 0);
    load_tile(1, 1);

    int stage = 0;
    for (int kt = 0; kt < nTiles; kt++) {
        if (kt + 2 < nTiles) {
            asm volatile("cp.async.wait_group 1;\n" ::: "memory");
        } else {
            asm volatile("cp.async.wait_group 0;\n" ::: "memory");
        }
        __syncthreads();
        if (kt + 2 < nTiles) {
            int s2 = stage + 2; if (s2 >= 3) s2 -= 3;
            load_tile(s2, kt + 2);
        }

        const uint32_t* as = reinterpret_cast<const uint32_t*>(smf + stage * STG_FLOATS);
        const uint32_t* bs = as + 4096;
        #pragma unroll
        for (int kk = 0; kk < 4; kk++) {
            const int c0 = kk * 8 + qcol;
            uint32_t af[4][4], bf[8][2];
            #pragma unroll
            for (int fm = 0; fm < 4; fm++) {
                int r0 = wm * 64 + fm * 16 + qrow;
                af[fm][0] = as[r0 * 32 + (c0 ^ sw)];
                af[fm][1] = as[(r0 + 8) * 32 + (c0 ^ sw)];
                af[fm][2] = as[r0 * 32 + ((c0 + 4) ^ sw)];
                af[fm][3] = as[(r0 + 8) * 32 + ((c0 + 4) ^ sw)];
            }
            #pragma unroll
            for (int fn = 0; fn < 8; fn++) {
                int ro = wn * 64 + fn * 8 + qrow;
                bf[fn][0] = bs[ro * 32 + (c0 ^ sw)];
                bf[fn][1] = bs[ro * 32 + ((c0 + 4) ^ sw)];
            }
            #pragma unroll
            for (int fm = 0; fm < 4; fm++)
                #pragma unroll
                for (int fn = 0; fn < 8; fn++)
                    mma8(acc[fm][fn], af[fm], bf[fn]);
        }
        __syncthreads();
        stage++; if (stage >= 3) stage = 0;
    }

    #pragma unroll
    for (int fm = 0; fm < 4; fm++) {
        int r0 = mBase + wm * 64 + fm * 16 + qrow;
        #pragma unroll
        for (int fn = 0; fn < 8; fn++) {
            int c0 = nBase + wn * 64 + fn * 8 + qcol * 2;
            if (MODE == 1) {
                float b0 = aux[c0], b1 = aux[c0 + 1];
                float2 v0 = make_float2(acc[fm][fn][0] + b0, acc[fm][fn][1] + b1);
                float2 v1 = make_float2(acc[fm][fn][2] + b0, acc[fm][fn][3] + b1);
                *reinterpret_cast<float2*>(C + (size_t)r0 * ldc + c0) = v0;
                *reinterpret_cast<float2*>(C + (size_t)(r0 + 8) * ldc + c0) = v1;
            } else {
                float s0 = aux[r0 * NEXP + (c0 >> 4)];
                float s1 = aux[(r0 + 8) * NEXP + (c0 >> 4)];
                float2 v0 = make_float2(tf32r(s0 * acc[fm][fn][0]), tf32r(s0 * acc[fm][fn][1]));
                float2 v1 = make_float2(tf32r(s1 * acc[fm][fn][2]), tf32r(s1 * acc[fm][fn][3]));
                *reinterpret_cast<float2*>(C + (size_t)r0 * ldc + c0) = v0;
                *reinterpret_cast<float2*>(C + (size_t)(r0 + 8) * ldc + c0) = v1;
            }
        }
    }
}

// ---------------- launch ------------------------------------------------------------
extern "C" void kernel_launch(void* const* d_in, const int* in_sizes, int n_in,
                              void* d_out, int out_size) {
    const float* x     = (const float*)d_in[0];
    const float* W     = (const float*)d_in[1];
    const float* bias  = (const float*)d_in[2];
    const float* rw1   = (const float*)d_in[3];
    const float* rb1   = (const float*)d_in[4];
    const float* rw2   = (const float*)d_in[5];
    const float* rb2   = (const float*)d_in[6];
    const float* A     = (const float*)d_in[7];
    const float* B     = (const float*)d_in[8];
    const float* gates = (const float*)d_in[9];
    float* out = (float*)d_out;

    const int GEMM_SMEM = 3 * STG_FLOATS * 4;          // 147456
    const int RH_SMEM   = (2 * 4096 + 2 * 32 * WS_STRIDE) * 4;  // 50176
    cudaFuncSetAttribute(gemm_tf32<0>, cudaFuncAttributeMaxDynamicSharedMemorySize, GEMM_SMEM);
    cudaFuncSetAttribute(gemm_tf32<1>, cudaFuncAttributeMaxDynamicSharedMemorySize, GEMM_SMEM);
    cudaFuncSetAttribute(hgemm_router, cudaFuncAttributeMaxDynamicSharedMemorySize, RH_SMEM);

    void *p_xt, *p_wmat, *p_acat, *p_wxa, *p_coeff;
    cudaGetSymbolAddress(&p_xt, g_xt);
    cudaGetSymbolAddress(&p_wmat, g_wmat);
    cudaGetSymbolAddress(&p_acat, g_acat);
    cudaGetSymbolAddress(&p_wxa, g_wxa);
    cudaGetSymbolAddress(&p_coeff, g_coeff);

    // 1) prep weights (tf32 W|Bcat, Acat) + rw1 transpose
    prep_kernel<<<20992, 256>>>(W, B, A, rw1);
    // 2) tf32-round x
    cvtx_kernel<<<32768, 256>>>(reinterpret_cast<const float4*>(x));
    // 3) router hidden: h = silu(x @ rw1^T + rb1), fp32
    hgemm_router<<<128, 256, RH_SMEM>>>(x, rb1);
    // 4) router top-2 -> g_coeff
    top2_kernel<<<2048, 256>>>(rw2, rb2, gates);
    // 5) xa = x @ Acat^T, epilogue wxa = tf32(coeff * xa)   [16384 x 256, K=2048]
    gemm_tf32<0><<<dim3(1, 128), 256, GEMM_SMEM>>>(
        (const float*)p_xt, DIN, DIN, nullptr, 0,
        (const float*)p_acat, DIN,
        (const float*)p_coeff, (float*)p_wxa, LORA, DIN);
    // 6) out = [x | wxa] @ [W^T ; Bcat] + bias              [16384 x 2048, K=2304]
    gemm_tf32<1><<<dim3(8, 128), 256, GEMM_SMEM>>>(
        (const float*)p_xt, DIN, DIN,
        (const float*)p_wxa, LORA,
        (const float*)p_wmat, KCAT,
        bias, out, DOUT, KCAT);
}